// round 1
// baseline (speedup 1.0000x reference)
#include <cuda_runtime.h>

// Problem constants
#define B_ 4
#define C_ 64
#define H_ 128
#define W_ 128
#define HW_ 16384
#define OCH_ 18        // offset channels = 2*K*K
#define COUT_ 64
#define K2_ 9

// Scratch (device globals — no allocation allowed)
__device__ float g_offs[B_ * OCH_ * H_ * W_];      // offset conv result
__device__ float g_wt[K2_ * C_ * COUT_];           // w_deform transposed: [tap][c][o]

// ---------------------------------------------------------------------------
// Kernel 0: transpose w_deform [o][c][ky][kx] -> g_wt[tap][c][o]
// ---------------------------------------------------------------------------
__global__ void k_transpose_w(const float* __restrict__ wd) {
    int idx = blockIdx.x * 256 + threadIdx.x;
    if (idx >= K2_ * C_ * COUT_) return;
    int tap = idx >> 12;          // /4096
    int r   = idx & 4095;
    int c   = r >> 6;
    int o   = r & 63;
    g_wt[idx] = wd[(o * C_ + c) * K2_ + tap];
}

// ---------------------------------------------------------------------------
// Kernel 1: offset conv (3x3, 64 -> 18, pad 1), one thread per output pixel.
// Weights staged in smem as ws[(c*3+ky)*56 + kx*18 + och] (padded rows of 56
// floats so each (c,ky) slab is 14 aligned float4's).
// ---------------------------------------------------------------------------
__global__ __launch_bounds__(256) void k_offset_conv(
    const float* __restrict__ x, const float* __restrict__ w_offset) {
    __shared__ float ws[192 * 56];
    int t = threadIdx.x;

    // Stage weights transposed
    for (int e = t; e < OCH_ * C_ * K2_; e += 256) {
        int och = e / (C_ * K2_);
        int r   = e % (C_ * K2_);
        int c   = r / K2_;
        int ky  = (r % K2_) / 3;
        int kx  = r % 3;
        ws[(c * 3 + ky) * 56 + kx * 18 + och] = w_offset[e];
    }
    __syncthreads();

    int idx = blockIdx.x * 256 + t;
    int b   = idx >> 14;
    int rem = idx & 16383;
    int h   = rem >> 7;
    int w   = rem & 127;

    float acc[OCH_];
#pragma unroll
    for (int i = 0; i < OCH_; ++i) acc[i] = 0.f;

    const float* xb = x + (size_t)b * C_ * HW_;

    for (int ky = 0; ky < 3; ++ky) {
        int y = h - 1 + ky;
        bool rv = (y >= 0) && (y < H_);
        for (int c = 0; c < C_; ++c) {
            const float* xr = xb + ((size_t)c * H_ + y) * W_;
            float xv0 = (rv && w >= 1)   ? xr[w - 1] : 0.f;
            float xv1 = rv               ? xr[w]     : 0.f;
            float xv2 = (rv && w <= 126) ? xr[w + 1] : 0.f;
            float xv[3] = {xv0, xv1, xv2};

            const float4* wrow = (const float4*)(ws + (c * 3 + ky) * 56);
            float wv[56];
#pragma unroll
            for (int j = 0; j < 14; ++j) {
                float4 q = wrow[j];
                wv[4 * j + 0] = q.x;
                wv[4 * j + 1] = q.y;
                wv[4 * j + 2] = q.z;
                wv[4 * j + 3] = q.w;
            }
#pragma unroll
            for (int kx = 0; kx < 3; ++kx) {
#pragma unroll
                for (int och = 0; och < OCH_; ++och) {
                    acc[och] += wv[kx * 18 + och] * xv[kx];
                }
            }
        }
    }

#pragma unroll
    for (int och = 0; och < OCH_; ++och) {
        g_offs[(((size_t)b * OCH_ + och) * H_ + h) * W_ + w] = acc[och];
    }
}

// ---------------------------------------------------------------------------
// Kernel 2: main deform-conv. One block per output row (b,h), 512 threads.
// Per tap: phase A computes v_tap[c][p] (64x128 smem) via bilinear gather,
// phase B accumulates out[o][p] += w_t[tap][c][o] * v[c][p] with an 8x2
// register tile per thread (16 accumulators).
// ---------------------------------------------------------------------------
__global__ __launch_bounds__(512, 2) void k_deform(
    const float* __restrict__ x, float* __restrict__ out) {
    __shared__ float vs[C_ * 128];    // 32 KB  v[c][p]
    __shared__ float wsm[C_ * 64];    // 16 KB  w[c][o] for current tap

    int bh = blockIdx.x;
    int b  = bh >> 7;
    int h  = bh & 127;
    int t  = threadIdx.x;

    // Phase B mapping
    int og = t >> 6;      // 0..7  -> o = og*8 .. og*8+7
    int pg = t & 63;      // p = pg*2, pg*2+1

    // Phase A mapping
    int pa = t & 127;     // pixel
    int qa = t >> 7;      // c chunk: qa*16 .. qa*16+15

    float acc[16];
#pragma unroll
    for (int i = 0; i < 16; ++i) acc[i] = 0.f;

    const float* xb = x + (size_t)b * C_ * HW_;

    for (int tap = 0; tap < K2_; ++tap) {
        int ky = tap / 3;
        int kx = tap % 3;

        // ---- phase A: bilinear gather into vs ----
        {
            const float* ob = g_offs + (((size_t)b * OCH_) * H_ + h) * W_;
            float dy = ob[(size_t)(2 * tap)     * HW_ + pa];
            float dx = ob[(size_t)(2 * tap + 1) * HW_ + pa];

            float py = (float)(h - 1 + ky) + dy;
            float px = (float)(pa - 1 + kx) + dx;
            float y0f = floorf(py);
            float x0f = floorf(px);
            float ly = py - y0f;
            float lx = px - x0f;
            int y0 = (int)y0f, x0 = (int)x0f;
            int y1 = y0 + 1,   x1 = x0 + 1;

            bool vy0 = (y0 >= 0) && (y0 < H_);
            bool vy1 = (y1 >= 0) && (y1 < H_);
            bool vx0 = (x0 >= 0) && (x0 < W_);
            bool vx1 = (x1 >= 0) && (x1 < W_);

            float w00 = (1.f - ly) * (1.f - lx) * ((vy0 && vx0) ? 1.f : 0.f);
            float w01 = (1.f - ly) * lx         * ((vy0 && vx1) ? 1.f : 0.f);
            float w10 = ly * (1.f - lx)         * ((vy1 && vx0) ? 1.f : 0.f);
            float w11 = ly * lx                 * ((vy1 && vx1) ? 1.f : 0.f);

            int y0c = min(max(y0, 0), H_ - 1);
            int y1c = min(max(y1, 0), H_ - 1);
            int x0c = min(max(x0, 0), W_ - 1);
            int x1c = min(max(x1, 0), W_ - 1);

            int i00 = y0c * W_ + x0c;
            int i01 = y0c * W_ + x1c;
            int i10 = y1c * W_ + x0c;
            int i11 = y1c * W_ + x1c;

            const float* xc = xb + (size_t)(qa * 16) * HW_;
            float* vrow = vs + (qa * 16) * 128 + pa;
#pragma unroll
            for (int c = 0; c < 16; ++c) {
                const float* pc = xc + (size_t)c * HW_;
                float val = w00 * pc[i00] + w01 * pc[i01] +
                            w10 * pc[i10] + w11 * pc[i11];
                vrow[c * 128] = val;
            }
        }

        // ---- stage w tile for this tap ----
        {
            const float4* src = (const float4*)(g_wt + (size_t)tap * C_ * COUT_);
            float4* dst = (float4*)wsm;
#pragma unroll
            for (int i = t; i < (C_ * COUT_) / 4; i += 512) dst[i] = src[i];
        }

        __syncthreads();

        // ---- phase B: register-tiled GEMM ----
        {
            const float2* vp = (const float2*)vs;
#pragma unroll 4
            for (int c = 0; c < C_; ++c) {
                float2 vv = vp[c * 64 + pg];
                float4 w0 = *(const float4*)(wsm + c * 64 + og * 8);
                float4 w1 = *(const float4*)(wsm + c * 64 + og * 8 + 4);
                acc[0]  += w0.x * vv.x;  acc[1]  += w0.x * vv.y;
                acc[2]  += w0.y * vv.x;  acc[3]  += w0.y * vv.y;
                acc[4]  += w0.z * vv.x;  acc[5]  += w0.z * vv.y;
                acc[6]  += w0.w * vv.x;  acc[7]  += w0.w * vv.y;
                acc[8]  += w1.x * vv.x;  acc[9]  += w1.x * vv.y;
                acc[10] += w1.y * vv.x;  acc[11] += w1.y * vv.y;
                acc[12] += w1.z * vv.x;  acc[13] += w1.z * vv.y;
                acc[14] += w1.w * vv.x;  acc[15] += w1.w * vv.y;
            }
        }

        __syncthreads();
    }

    // ---- write out ----
    int p = pg * 2;
#pragma unroll
    for (int j = 0; j < 8; ++j) {
        int o = og * 8 + j;
        float2 r;
        r.x = acc[2 * j];
        r.y = acc[2 * j + 1];
        *(float2*)(out + (((size_t)b * COUT_ + o) * H_ + h) * W_ + p) = r;
    }
}

// ---------------------------------------------------------------------------
extern "C" void kernel_launch(void* const* d_in, const int* in_sizes, int n_in,
                              void* d_out, int out_size) {
    const float* x        = (const float*)d_in[0];
    const float* w_offset = (const float*)d_in[1];
    const float* w_deform = (const float*)d_in[2];
    float* out = (float*)d_out;

    k_transpose_w<<<(K2_ * C_ * COUT_ + 255) / 256, 256>>>(w_deform);
    k_offset_conv<<<(B_ * H_ * W_) / 256, 256>>>(x, w_offset);
    k_deform<<<B_ * H_, 512>>>(x, out);
}

// round 2
// speedup vs baseline: 1.1170x; 1.1170x over previous
#include <cuda_runtime.h>

// Problem constants
#define B_ 4
#define C_ 64
#define H_ 128
#define W_ 128
#define HW_ 16384
#define OCH_ 18        // offset channels = 2*K*K
#define COUT_ 64
#define K2_ 9

// Scratch (device globals — no allocation allowed)
__device__ float g_offs[B_ * OCH_ * H_ * W_];      // offset conv result
__device__ float g_wt[K2_ * C_ * COUT_];           // w_deform transposed: [tap][c][o]

// ---- packed f32x2 helpers (FFMA2: 2 fp32 FMA per issue slot) ----
__device__ __forceinline__ unsigned long long pk2(float a, float b) {
    unsigned long long r;
    asm("mov.b64 %0, {%1, %2};" : "=l"(r) : "f"(a), "f"(b));
    return r;
}
__device__ __forceinline__ unsigned long long fma2(unsigned long long a,
                                                   unsigned long long b,
                                                   unsigned long long c) {
    unsigned long long d;
    asm("fma.rn.f32x2 %0, %1, %2, %3;" : "=l"(d) : "l"(a), "l"(b), "l"(c));
    return d;
}
__device__ __forceinline__ float2 upk(unsigned long long a) {
    float2 f;
    asm("mov.b64 {%0, %1}, %2;" : "=f"(f.x), "=f"(f.y) : "l"(a));
    return f;
}

// ---------------------------------------------------------------------------
// Kernel 0: transpose w_deform [o][c][ky][kx] -> g_wt[tap][c][o]
// ---------------------------------------------------------------------------
__global__ void k_transpose_w(const float* __restrict__ wd) {
    int idx = blockIdx.x * 256 + threadIdx.x;
    if (idx >= K2_ * C_ * COUT_) return;
    int tap = idx >> 12;          // /4096
    int r   = idx & 4095;
    int c   = r >> 6;
    int o   = r & 63;
    g_wt[idx] = wd[(o * C_ + c) * K2_ + tap];
}

// ---------------------------------------------------------------------------
// Kernel 1: offset conv (3x3, 64 -> 18, pad 1), one thread per output pixel.
// Weights staged in smem as ws[(c*3+ky)*56 + kx*18 + och] (padded rows of 56
// floats). Inner product done with packed f32x2 FMAs over och pairs.
// ---------------------------------------------------------------------------
__global__ __launch_bounds__(256) void k_offset_conv(
    const float* __restrict__ x, const float* __restrict__ w_offset) {
    __shared__ float ws[192 * 56];
    int t = threadIdx.x;

    // Stage weights transposed
    for (int e = t; e < OCH_ * C_ * K2_; e += 256) {
        int och = e / (C_ * K2_);
        int r   = e % (C_ * K2_);
        int c   = r / K2_;
        int ky  = (r % K2_) / 3;
        int kx  = r % 3;
        ws[(c * 3 + ky) * 56 + kx * 18 + och] = w_offset[e];
    }
    __syncthreads();

    int idx = blockIdx.x * 256 + t;
    int b   = idx >> 14;
    int rem = idx & 16383;
    int h   = rem >> 7;
    int w   = rem & 127;

    unsigned long long acc2[9];   // 18 och as 9 f32x2 pairs
#pragma unroll
    for (int i = 0; i < 9; ++i) acc2[i] = 0ULL;

    const float* xb = x + (size_t)b * C_ * HW_;

    for (int ky = 0; ky < 3; ++ky) {
        int y = h - 1 + ky;
        bool rv = (y >= 0) && (y < H_);
        for (int c = 0; c < C_; ++c) {
            const float* xr = xb + ((size_t)c * H_ + y) * W_;
            float xv0 = (rv && w >= 1)   ? xr[w - 1] : 0.f;
            float xv1 = rv               ? xr[w]     : 0.f;
            float xv2 = (rv && w <= 126) ? xr[w + 1] : 0.f;

            // Load the 56-float weight row as 14x LDS.128, viewed as u64 pairs.
            const ulonglong2* wrow =
                (const ulonglong2*)(ws + (c * 3 + ky) * 56);
            unsigned long long wv2[28];
#pragma unroll
            for (int j = 0; j < 14; ++j) {
                ulonglong2 q = wrow[j];
                wv2[2 * j]     = q.x;
                wv2[2 * j + 1] = q.y;
            }

            unsigned long long xp0 = pk2(xv0, xv0);
            unsigned long long xp1 = pk2(xv1, xv1);
            unsigned long long xp2 = pk2(xv2, xv2);
#pragma unroll
            for (int j = 0; j < 9; ++j) {
                acc2[j] = fma2(wv2[j],      xp0, acc2[j]);
                acc2[j] = fma2(wv2[9 + j],  xp1, acc2[j]);
                acc2[j] = fma2(wv2[18 + j], xp2, acc2[j]);
            }
        }
    }

#pragma unroll
    for (int j = 0; j < 9; ++j) {
        float2 r = upk(acc2[j]);
        g_offs[(((size_t)b * OCH_ + 2 * j)     * H_ + h) * W_ + w] = r.x;
        g_offs[(((size_t)b * OCH_ + 2 * j + 1) * H_ + h) * W_ + w] = r.y;
    }
}

// ---------------------------------------------------------------------------
// Kernel 2: main deform-conv. One block per output row (b,h), 512 threads.
// Per tap: phase A computes v_tap[c][p] (64x128 smem) via bilinear gather,
// phase B accumulates out[o][p] += w_t[tap][c][o] * v[c][p] with 8 packed
// f32x2 accumulators per thread (8 o x 2 p, packed over o).
// ---------------------------------------------------------------------------
__global__ __launch_bounds__(512, 2) void k_deform(
    const float* __restrict__ x, float* __restrict__ out) {
    __shared__ float vs[C_ * 128];    // 32 KB  v[c][p]
    __shared__ float wsm[C_ * 64];    // 16 KB  w[c][o] for current tap

    int bh = blockIdx.x;
    int b  = bh >> 7;
    int h  = bh & 127;
    int t  = threadIdx.x;

    // Phase B mapping
    int og = t >> 6;      // 0..7  -> o = og*8 .. og*8+7 (uniform within warp)
    int pg = t & 63;      // p = pg*2, pg*2+1

    // Phase A mapping
    int pa = t & 127;     // pixel
    int qa = t >> 7;      // c chunk: qa*16 .. qa*16+15

    // acc2[opair*2 + pslot] = f32x2 over (o = og*8+2*opair, +1) at p = pg*2+pslot
    unsigned long long acc2[8];
#pragma unroll
    for (int i = 0; i < 8; ++i) acc2[i] = 0ULL;

    const float* xb = x + (size_t)b * C_ * HW_;

    for (int tap = 0; tap < K2_; ++tap) {
        int ky = tap / 3;
        int kx = tap % 3;

        // ---- phase A: bilinear gather into vs ----
        {
            const float* ob = g_offs + (((size_t)b * OCH_) * H_ + h) * W_;
            float dy = ob[(size_t)(2 * tap)     * HW_ + pa];
            float dx = ob[(size_t)(2 * tap + 1) * HW_ + pa];

            float py = (float)(h - 1 + ky) + dy;
            float px = (float)(pa - 1 + kx) + dx;
            float y0f = floorf(py);
            float x0f = floorf(px);
            float ly = py - y0f;
            float lx = px - x0f;
            int y0 = (int)y0f, x0 = (int)x0f;
            int y1 = y0 + 1,   x1 = x0 + 1;

            bool vy0 = (y0 >= 0) && (y0 < H_);
            bool vy1 = (y1 >= 0) && (y1 < H_);
            bool vx0 = (x0 >= 0) && (x0 < W_);
            bool vx1 = (x1 >= 0) && (x1 < W_);

            float w00 = (1.f - ly) * (1.f - lx) * ((vy0 && vx0) ? 1.f : 0.f);
            float w01 = (1.f - ly) * lx         * ((vy0 && vx1) ? 1.f : 0.f);
            float w10 = ly * (1.f - lx)         * ((vy1 && vx0) ? 1.f : 0.f);
            float w11 = ly * lx                 * ((vy1 && vx1) ? 1.f : 0.f);

            int y0c = min(max(y0, 0), H_ - 1);
            int y1c = min(max(y1, 0), H_ - 1);
            int x0c = min(max(x0, 0), W_ - 1);
            int x1c = min(max(x1, 0), W_ - 1);

            int i00 = y0c * W_ + x0c;
            int i01 = y0c * W_ + x1c;
            int i10 = y1c * W_ + x0c;
            int i11 = y1c * W_ + x1c;

            const float* xc = xb + (size_t)(qa * 16) * HW_;
            float* vrow = vs + (qa * 16) * 128 + pa;
#pragma unroll
            for (int c = 0; c < 16; ++c) {
                const float* pc = xc + (size_t)c * HW_;
                float val = w00 * pc[i00] + w01 * pc[i01] +
                            w10 * pc[i10] + w11 * pc[i11];
                vrow[c * 128] = val;
            }
        }

        // ---- stage w tile for this tap ----
        {
            const float4* src = (const float4*)(g_wt + (size_t)tap * C_ * COUT_);
            float4* dst = (float4*)wsm;
#pragma unroll
            for (int i = t; i < (C_ * COUT_) / 4; i += 512) dst[i] = src[i];
        }

        __syncthreads();

        // ---- phase B: register-tiled GEMM with packed f32x2 FMAs ----
        {
            const float2* vp = (const float2*)vs;
#pragma unroll 4
            for (int c = 0; c < C_; ++c) {
                float2 vv = vp[c * 64 + pg];
                const ulonglong2* wp =
                    (const ulonglong2*)(wsm + c * 64 + og * 8);
                ulonglong2 wa = wp[0];   // {w(o0),w(o1)}, {w(o2),w(o3)}
                ulonglong2 wb = wp[1];   // {w(o4),w(o5)}, {w(o6),w(o7)}

                unsigned long long vx2 = pk2(vv.x, vv.x);
                unsigned long long vy2 = pk2(vv.y, vv.y);

                acc2[0] = fma2(wa.x, vx2, acc2[0]);
                acc2[1] = fma2(wa.x, vy2, acc2[1]);
                acc2[2] = fma2(wa.y, vx2, acc2[2]);
                acc2[3] = fma2(wa.y, vy2, acc2[3]);
                acc2[4] = fma2(wb.x, vx2, acc2[4]);
                acc2[5] = fma2(wb.x, vy2, acc2[5]);
                acc2[6] = fma2(wb.y, vx2, acc2[6]);
                acc2[7] = fma2(wb.y, vy2, acc2[7]);
            }
        }

        __syncthreads();
    }

    // ---- write out ----
    int p = pg * 2;
#pragma unroll
    for (int opair = 0; opair < 4; ++opair) {
        float2 a0 = upk(acc2[opair * 2]);      // pixel p  : (o_even, o_odd)
        float2 a1 = upk(acc2[opair * 2 + 1]);  // pixel p+1: (o_even, o_odd)
        int oe = og * 8 + opair * 2;
        float2 r0; r0.x = a0.x; r0.y = a1.x;
        float2 r1; r1.x = a0.y; r1.y = a1.y;
        *(float2*)(out + (((size_t)b * COUT_ + oe)     * H_ + h) * W_ + p) = r0;
        *(float2*)(out + (((size_t)b * COUT_ + oe + 1) * H_ + h) * W_ + p) = r1;
    }
}

// ---------------------------------------------------------------------------
extern "C" void kernel_launch(void* const* d_in, const int* in_sizes, int n_in,
                              void* d_out, int out_size) {
    const float* x        = (const float*)d_in[0];
    const float* w_offset = (const float*)d_in[1];
    const float* w_deform = (const float*)d_in[2];
    float* out = (float*)d_out;

    k_transpose_w<<<(K2_ * C_ * COUT_ + 255) / 256, 256>>>(w_deform);
    k_offset_conv<<<(B_ * H_ * W_) / 256, 256>>>(x, w_offset);
    k_deform<<<B_ * H_, 512>>>(x, out);
}